// round 9
// baseline (speedup 1.0000x reference)
#include <cuda_runtime.h>

#define N 512
#define D 512

__device__ float g_u[N * D];    // u[i][h]
__device__ float g_vT[D * N];   // v^T[h][j] (+W0_b folded)
__device__ float g_a[N * N];    // softmax rows

typedef unsigned long long u64;

// ---- packed f32x2 helpers (sm_100+) --------------------------------------
__device__ __forceinline__ void fma2(u64& d, u64 a, u64 b) {
    asm("fma.rn.f32x2 %0, %1, %2, %3;" : "=l"(d) : "l"(a), "l"(b), "l"(d));
}
__device__ __forceinline__ u64 add2(u64 a, u64 b) {
    u64 d; asm("add.rn.f32x2 %0, %1, %2;" : "=l"(d) : "l"(a), "l"(b)); return d;
}
__device__ __forceinline__ u64 pk(float x, float y) {
    u64 d; asm("mov.b64 %0, {%1, %2};" : "=l"(d) : "f"(x), "f"(y)); return d;
}
__device__ __forceinline__ float2 upk(u64 v) {
    float2 d; asm("mov.b64 {%0, %1}, %2;" : "=f"(d.x), "=f"(d.y) : "l"(v)); return d;
}
__device__ __forceinline__ void cpa16(float* dst, const float* src) {
    unsigned sa = (unsigned)__cvta_generic_to_shared(dst);
    asm volatile("cp.async.cg.shared.global [%0], [%1], 16;" :: "r"(sa), "l"(src));
}

// ---------------------------------------------------------------------------
// Kernel 1: fused u|v NT-GEMM, NO k-split. 64x64 tiles, grid (16,8)=128 CTAs,
// 256 threads, thread 4x4 (k-pair packed FFMA2), cp.async double-buffered
// 32-k chunks. Epilogue: u -> g_u natural; v -> g_vT transposed + bias.
// ---------------------------------------------------------------------------
#define GST 36

__global__ __launch_bounds__(256) void uv_gemm_kernel(
    const float* __restrict__ he, const float* __restrict__ W,
    const float* __restrict__ b)
{
    __shared__ float as[2][64 * GST];
    __shared__ float bs[2][64 * GST];

    const int n0 = blockIdx.x * 64;          // 0..1023
    const int i0 = blockIdx.y * 64;
    const int which = (n0 >= 512);
    const int koff = which ? 512 : 0;
    const int nr0 = n0 & 511;                // h-row base
    const int tid = threadIdx.x;
    const int tx = tid & 15;
    const int ty = tid >> 4;

    // loader mapping: 2 f4 per thread per tile
    const int lr0 = tid >> 3;                // 0..31
    const int lkq = (tid & 7) << 2;

    // prologue chunk 0
    #pragma unroll
    for (int q = 0; q < 2; q++) {
        const int r = lr0 + 32 * q;
        cpa16(&as[0][r * GST + lkq], &he[(size_t)(i0 + r) * D + lkq]);
        cpa16(&bs[0][r * GST + lkq], &W[(size_t)(nr0 + r) * 1024 + koff + lkq]);
    }
    asm volatile("cp.async.commit_group;");

    u64 acc[4][4] = {};

    for (int ch = 0; ch < 16; ch++) {
        if (ch + 1 < 16) {
            const int kc = (ch + 1) * 32;
            float* ad = as[(ch + 1) & 1];
            float* bd = bs[(ch + 1) & 1];
            #pragma unroll
            for (int q = 0; q < 2; q++) {
                const int r = lr0 + 32 * q;
                cpa16(&ad[r * GST + lkq], &he[(size_t)(i0 + r) * D + kc + lkq]);
                cpa16(&bd[r * GST + lkq], &W[(size_t)(nr0 + r) * 1024 + koff + kc + lkq]);
            }
            asm volatile("cp.async.commit_group;");
            asm volatile("cp.async.wait_group 1;");
        } else {
            asm volatile("cp.async.wait_group 0;");
        }
        __syncthreads();

        const float* ab = as[ch & 1];
        const float* bb = bs[ch & 1];
        #pragma unroll
        for (int kk = 0; kk < 32; kk += 4) {
            ulonglong2 av[4], bv[4];
            #pragma unroll
            for (int r = 0; r < 4; r++)
                av[r] = *(const ulonglong2*)&ab[(ty + 16 * r) * GST + kk];
            #pragma unroll
            for (int c = 0; c < 4; c++)
                bv[c] = *(const ulonglong2*)&bb[(tx + 16 * c) * GST + kk];
            #pragma unroll
            for (int r = 0; r < 4; r++)
                #pragma unroll
                for (int c = 0; c < 4; c++) {
                    fma2(acc[r][c], av[r].x, bv[c].x);
                    fma2(acc[r][c], av[r].y, bv[c].y);
                }
        }
        __syncthreads();
    }

    if (!which) {
        #pragma unroll
        for (int r = 0; r < 4; r++) {
            const int row = i0 + ty + 16 * r;
            #pragma unroll
            for (int c = 0; c < 4; c++) {
                float2 f = upk(acc[r][c]);
                g_u[(size_t)row * D + nr0 + tx + 16 * c] = f.x + f.y;
            }
        }
    } else {
        #pragma unroll
        for (int c = 0; c < 4; c++) {
            const int hh = nr0 + tx + 16 * c;
            const float bias = __ldg(&b[hh]);
            #pragma unroll
            for (int r = 0; r < 4; r++) {
                float2 f = upk(acc[r][c]);
                g_vT[(size_t)hh * N + i0 + ty + 16 * r] = f.x + f.y + bias;
            }
        }
    }
}

// ---------------------------------------------------------------------------
// Kernel 2: pairwise + softmax. CTA = 4 i-rows x 512 j, 256 threads
// (thread = 4 i x j-pair {2t,2t+1}). v streamed directly from g_vT via
// LDG.64 (no smem staging, no mainloop syncs); u/w1 pre-duplicated {x,x}
// u64 broadcasts in smem.
// ---------------------------------------------------------------------------
__global__ __launch_bounds__(256) void pairwise_kernel(
    const float* __restrict__ w1)
{
    __shared__ u64 u2s[4 * 512];
    __shared__ u64 w2s[512];
    __shared__ float p_s[4 * 512];
    __shared__ float inv_s[4];

    const int tid = threadIdx.x;
    const int i0 = blockIdx.x * 4;

    // stage u (4 rows) and w1 as duplicated pairs
    {
        const float4* usrc = (const float4*)(g_u + (size_t)i0 * D);
        #pragma unroll
        for (int e = 0; e < 2; e++) {
            const int m = tid + 256 * e;           // 0..511 f4
            float4 f = usrc[m];
            u2s[m * 4 + 0] = pk(f.x, f.x);
            u2s[m * 4 + 1] = pk(f.y, f.y);
            u2s[m * 4 + 2] = pk(f.z, f.z);
            u2s[m * 4 + 3] = pk(f.w, f.w);
        }
        if (tid < 128) {
            float4 f = ((const float4*)w1)[tid];
            w2s[tid * 4 + 0] = pk(f.x, f.x);
            w2s[tid * 4 + 1] = pk(f.y, f.y);
            w2s[tid * 4 + 2] = pk(f.z, f.z);
            w2s[tid * 4 + 3] = pk(f.w, f.w);
        }
    }
    __syncthreads();

    u64 acc[4] = {};
    const u64* vp = (const u64*)g_vT + tid;        // j-pair column, stride 256/h

    #pragma unroll 8
    for (int h = 0; h < D; h++) {
        const u64 vv = __ldg(vp + (size_t)h * 256);
        const u64 ww = w2s[h];
        #pragma unroll
        for (int i = 0; i < 4; i++) {
            u64 t = add2(u2s[i * 512 + h], vv);
            float2 f = upk(t);
            fma2(acc[i], pk(fmaxf(f.x, 0.f), fmaxf(f.y, 0.f)), ww);
        }
    }

    #pragma unroll
    for (int i = 0; i < 4; i++)
        ((u64*)(p_s + i * 512))[tid] = acc[i];
    __syncthreads();

    // softmax: warps 0..3 handle rows 0..3
    const int warp = tid >> 5, lane = tid & 31;
    if (warp < 4) {
        float* prow = p_s + warp * 512;
        float m = -1e30f;
        for (int j = lane; j < N; j += 32) m = fmaxf(m, prow[j]);
        #pragma unroll
        for (int o = 16; o; o >>= 1) m = fmaxf(m, __shfl_xor_sync(0xffffffffu, m, o));
        float s = 0.f;
        for (int j = lane; j < N; j += 32) {
            float e = __expf(prow[j] - m);
            prow[j] = e;
            s += e;
        }
        #pragma unroll
        for (int o = 16; o; o >>= 1) s += __shfl_xor_sync(0xffffffffu, s, o);
        if (lane == 0) inv_s[warp] = 1.f / s;
    }
    __syncthreads();

    #pragma unroll
    for (int e = 0; e < 2; e++) {
        const int m = tid + 256 * e;                // 4x128 f4
        const int i = m >> 7, jj = m & 127;
        float4 v = ((const float4*)(p_s + i * 512))[jj];
        const float s = inv_s[i];
        v.x *= s; v.y *= s; v.z *= s; v.w *= s;
        ((float4*)(g_a + (size_t)(i0 + i) * N))[jj] = v;
    }
}

// ---------------------------------------------------------------------------
// Kernel 3: out = a @ he, c-pair packed. Tile 32i x 64c, 256 threads
// (thread = 2i x 2 c-pairs), grid (8,16)=128 CTAs. he rows via cp.async,
// a duplicated {x,x} in smem. Double-buffered 32-k chunks.
// ---------------------------------------------------------------------------
#define OHST 68

__global__ __launch_bounds__(256) void out_gemm_kernel(
    const float* __restrict__ he, float* __restrict__ out)
{
    __shared__ float he_s[2][32 * OHST];  // [k][c] natural rows + pad
    __shared__ u64  a2s[2][32 * 32];      // [i][k] duplicated pairs

    const int c0 = blockIdx.x * 64;
    const int i0 = blockIdx.y * 32;
    const int tid = threadIdx.x;
    const int tx = tid & 15;              // c block: 4*tx
    const int ty = tid >> 4;              // i rows ty, ty+16

    const int ar = tid >> 3;              // 0..31
    const int akq = (tid & 7) << 2;       // 0..28

    float areg[4];

    // prologue
    {
        float4 v = *(const float4*)&g_a[(size_t)(i0 + ar) * N + akq];
        areg[0] = v.x; areg[1] = v.y; areg[2] = v.z; areg[3] = v.w;
        #pragma unroll
        for (int e = 0; e < 4; e++)
            a2s[0][ar * 32 + akq + e] = pk(areg[e], areg[e]);
        #pragma unroll
        for (int q = 0; q < 2; q++) {
            const int m = tid + 256 * q;
            const int k = m >> 4, cq = (m & 15) << 2;
            cpa16(&he_s[0][k * OHST + cq], &he[(size_t)k * D + c0 + cq]);
        }
        asm volatile("cp.async.commit_group;");
    }

    u64 acc[2][2] = {};

    for (int ch = 0; ch < 16; ch++) {
        if (ch + 1 < 16) {
            const int k0 = (ch + 1) * 32;
            float4 v = *(const float4*)&g_a[(size_t)(i0 + ar) * N + k0 + akq];
            areg[0] = v.x; areg[1] = v.y; areg[2] = v.z; areg[3] = v.w;
            float* hd = he_s[(ch + 1) & 1];
            #pragma unroll
            for (int q = 0; q < 2; q++) {
                const int m = tid + 256 * q;
                const int k = m >> 4, cq = (m & 15) << 2;
                cpa16(&hd[k * OHST + cq], &he[(size_t)(k0 + k) * D + c0 + cq]);
            }
            asm volatile("cp.async.commit_group;");
            asm volatile("cp.async.wait_group 1;");
        } else {
            asm volatile("cp.async.wait_group 0;");
        }
        __syncthreads();

        const float* hb = he_s[ch & 1];
        const u64* ab = a2s[ch & 1];
        #pragma unroll
        for (int k = 0; k < 32; k++) {
            ulonglong2 bb = *(const ulonglong2*)&hb[k * OHST + 4 * tx];
            #pragma unroll
            for (int r = 0; r < 2; r++) {
                const u64 aa = ab[(ty + 16 * r) * 32 + k];
                fma2(acc[r][0], aa, bb.x);
                fma2(acc[r][1], aa, bb.y);
            }
        }

        if (ch + 1 < 16) {
            #pragma unroll
            for (int e = 0; e < 4; e++)
                a2s[(ch + 1) & 1][ar * 32 + akq + e] = pk(areg[e], areg[e]);
        }
        __syncthreads();
    }

    #pragma unroll
    for (int r = 0; r < 2; r++) {
        float2 f0 = upk(acc[r][0]);
        float2 f1 = upk(acc[r][1]);
        float4 o = make_float4(f0.x, f0.y, f1.x, f1.y);
        *(float4*)&out[(size_t)(i0 + ty + 16 * r) * D + c0 + 4 * tx] = o;
    }
}

// ---------------------------------------------------------------------------
extern "C" void kernel_launch(void* const* d_in, const int* in_sizes, int n_in,
                              void* d_out, int out_size)
{
    const float* he  = (const float*)d_in[0];   // (512, 512)
    const float* W0w = (const float*)d_in[1];   // (512, 1024)
    const float* W0b = (const float*)d_in[2];   // (512,)
    const float* W1w = (const float*)d_in[3];   // (1, 512)
    // d_in[4] = W1_b: softmax shift-invariant -> unused
    float* out = (float*)d_out;

    dim3 gG(16, 8);                              // 128 CTAs x 256 thr
    uv_gemm_kernel<<<gG, 256>>>(he, W0w, W0b);

    pairwise_kernel<<<N / 4, 256>>>(W1w);        // 128 CTAs x 256 thr

    dim3 gC(8, 16);                              // 128 CTAs x 256 thr
    out_gemm_kernel<<<gC, 256>>>(he, out);
}

// round 12
// speedup vs baseline: 1.7820x; 1.7820x over previous
#include <cuda_runtime.h>

#define N 512
#define D 512

__device__ float g_u[N * D];            // u[i][h]
__device__ float g_vT[D * N];           // v^T[h][j] (+W0_b folded)
__device__ float g_a[N * N];            // softmax rows
__device__ float g_part[4 * N * 1024];  // k-split partials

typedef unsigned long long u64;

// ---- packed f32x2 helpers (sm_100+) --------------------------------------
__device__ __forceinline__ void fma2(u64& d, u64 a, u64 b) {
    asm("fma.rn.f32x2 %0, %1, %2, %3;" : "=l"(d) : "l"(a), "l"(b), "l"(d));
}
__device__ __forceinline__ u64 add2(u64 a, u64 b) {
    u64 d; asm("add.rn.f32x2 %0, %1, %2;" : "=l"(d) : "l"(a), "l"(b)); return d;
}
__device__ __forceinline__ u64 pk(float x, float y) {
    u64 d; asm("mov.b64 %0, {%1, %2};" : "=l"(d) : "f"(x), "f"(y)); return d;
}
__device__ __forceinline__ float2 upk(u64 v) {
    float2 d; asm("mov.b64 {%0, %1}, %2;" : "=f"(d.x), "=f"(d.y) : "l"(v)); return d;
}
__device__ __forceinline__ void cpa16(float* dst, const float* src) {
    unsigned sa = (unsigned)__cvta_generic_to_shared(dst);
    asm volatile("cp.async.cg.shared.global [%0], [%1], 16;" :: "r"(sa), "l"(src));
}

// ---------------------------------------------------------------------------
// Kernel 1: fused u|v GEMM, k-split 4. Tile 128x128, 256 threads, 8x8/thread
// (crossbar-balanced: 64B LDS per fma2). grid (8,4,4)=128 CTAs.
// ---------------------------------------------------------------------------
#define GST 36

__global__ __launch_bounds__(256) void uv_gemm_kernel(
    const float* __restrict__ he, const float* __restrict__ W)
{
    extern __shared__ float sm[];
    float* as = sm;                    // [2][128*GST]
    float* bs = sm + 2 * 128 * GST;    // [2][128*GST]

    const int n0 = blockIdx.x * 128;
    const int i0 = blockIdx.y * 128;
    const int kz = blockIdx.z;
    const int kbase = kz * 128;
    const int koff = (n0 >= 512) ? 512 : 0;
    const int nrow0 = n0 & 511;
    const int tid = threadIdx.x;
    const int tx = tid & 15;
    const int ty = tid >> 4;

    // prologue chunk 0
    #pragma unroll
    for (int q = 0; q < 4; q++) {
        const int f = 4 * tid + q;
        const int r = f >> 3, kq = (f & 7) << 2;
        cpa16(&as[r * GST + kq], &he[(size_t)(i0 + r) * D + kbase + kq]);
        cpa16(&bs[r * GST + kq], &W[(size_t)(nrow0 + r) * (2 * D) + koff + kbase + kq]);
    }
    asm volatile("cp.async.commit_group;");

    u64 acc[8][8] = {};

    for (int ch = 0; ch < 4; ch++) {
        if (ch + 1 < 4) {
            float* ad = as + ((ch + 1) & 1) * 128 * GST;
            float* bd = bs + ((ch + 1) & 1) * 128 * GST;
            const int kc = kbase + (ch + 1) * 32;
            #pragma unroll
            for (int q = 0; q < 4; q++) {
                const int f = 4 * tid + q;
                const int r = f >> 3, kq = (f & 7) << 2;
                cpa16(&ad[r * GST + kq], &he[(size_t)(i0 + r) * D + kc + kq]);
                cpa16(&bd[r * GST + kq], &W[(size_t)(nrow0 + r) * (2 * D) + koff + kc + kq]);
            }
            asm volatile("cp.async.commit_group;");
            asm volatile("cp.async.wait_group 1;");
        } else {
            asm volatile("cp.async.wait_group 0;");
        }
        __syncthreads();

        const float* ab = as + (ch & 1) * 128 * GST;
        const float* bb = bs + (ch & 1) * 128 * GST;
        #pragma unroll
        for (int kk = 0; kk < 32; kk += 2) {
            u64 av[8], bv[8];
            #pragma unroll
            for (int r = 0; r < 8; r++)
                av[r] = *(const u64*)&ab[(ty + 16 * r) * GST + kk];
            #pragma unroll
            for (int c = 0; c < 8; c++)
                bv[c] = *(const u64*)&bb[(tx + 16 * c) * GST + kk];
            #pragma unroll
            for (int r = 0; r < 8; r++)
                #pragma unroll
                for (int c = 0; c < 8; c++)
                    fma2(acc[r][c], av[r], bv[c]);
        }
        __syncthreads();
    }

    #pragma unroll
    for (int r = 0; r < 8; r++) {
        const size_t row = i0 + ty + 16 * r;
        float* dst = g_part + (size_t)kz * (N * 1024) + row * 1024 + n0;
        #pragma unroll
        for (int c = 0; c < 8; c++) {
            float2 f = upk(acc[r][c]);
            dst[tx + 16 * c] = f.x + f.y;
        }
    }
}

// ---------------------------------------------------------------------------
// Kernel 2: reduce k-split partials -> g_u, g_vT (+bias). Deterministic.
// ---------------------------------------------------------------------------
__global__ __launch_bounds__(256) void reduce_kernel(const float* __restrict__ b)
{
    const int tid = threadIdx.x;
    #pragma unroll
    for (int e = 0; e < 4; e++) {
        const int idx4 = blockIdx.x * 1024 + e * 256 + tid;
        float4 s = *(const float4*)&g_part[(size_t)idx4 * 4];
        #pragma unroll
        for (int kz = 1; kz < 4; kz++) {
            float4 p = *(const float4*)&g_part[(size_t)kz * (N * 1024) + (size_t)idx4 * 4];
            s.x += p.x; s.y += p.y; s.z += p.z; s.w += p.w;
        }
        const int base = idx4 * 4;
        const int i = base >> 10;
        const int h = base & 1023;
        if (h < 512) {
            *(float4*)&g_u[(size_t)i * D + h] = s;
        } else {
            const int hh = h - 512;
            g_vT[(size_t)(hh + 0) * N + i] = s.x + b[hh + 0];
            g_vT[(size_t)(hh + 1) * N + i] = s.y + b[hh + 1];
            g_vT[(size_t)(hh + 2) * N + i] = s.z + b[hh + 2];
            g_vT[(size_t)(hh + 3) * N + i] = s.w + b[hh + 3];
        }
    }
}

// ---------------------------------------------------------------------------
// Kernel 3: pairwise + softmax. CTA = 4 i x 512 j, 256 thr (thread = 4i x
// 1 j-pair). v staged via cp.async (PHCH=8 -> 61KB -> 2 CTAs/SM); u/w as
// duplicated {x,x} u64 pairs read with LDS.128 over (h,h+1).
// ---------------------------------------------------------------------------
#define PHCH 8

__global__ __launch_bounds__(256) void pairwise_kernel(
    const float* __restrict__ w1)
{
    extern __shared__ float sm[];
    float* v_s   = sm;                              // [2][PHCH][512]
    u64*  u2s    = (u64*)(sm + 2 * PHCH * 512);     // [4*512]
    u64*  w2s    = u2s + 4 * 512;                   // [512]
    float* p_s   = (float*)(w2s + 512);             // [4][512]
    float* inv_s = p_s + 4 * 512;                   // [4]

    const int tid = threadIdx.x;
    const int i0 = blockIdx.x * 4;

    // stage u (4 rows) and w1 as duplicated {x,x} pairs
    {
        const float4* usrc = (const float4*)(g_u + (size_t)i0 * D);
        #pragma unroll
        for (int e = 0; e < 2; e++) {
            const int m = tid + 256 * e;            // 0..511 f4
            float4 f = usrc[m];
            u2s[m * 4 + 0] = pk(f.x, f.x);
            u2s[m * 4 + 1] = pk(f.y, f.y);
            u2s[m * 4 + 2] = pk(f.z, f.z);
            u2s[m * 4 + 3] = pk(f.w, f.w);
        }
        if (tid < 128) {
            float4 f = ((const float4*)w1)[tid];
            w2s[tid * 4 + 0] = pk(f.x, f.x);
            w2s[tid * 4 + 1] = pk(f.y, f.y);
            w2s[tid * 4 + 2] = pk(f.z, f.z);
            w2s[tid * 4 + 3] = pk(f.w, f.w);
        }
    }

    // prologue: v chunk 0 (PHCH rows x 512 j = 1024 f4, 4 per thread)
    #pragma unroll
    for (int q = 0; q < PHCH / 2; q++) {
        const int m = tid + 256 * q;
        const int r = m >> 7, c4 = (m & 127) << 2;
        cpa16(v_s + r * 512 + c4, g_vT + (size_t)r * N + c4);
    }
    asm volatile("cp.async.commit_group;");

    u64 acc[4] = {};

    for (int ch = 0; ch < D / PHCH; ch++) {
        if (ch + 1 < D / PHCH) {
            float* buf = v_s + ((ch + 1) & 1) * PHCH * 512;
            const float* src = g_vT + (size_t)(ch + 1) * PHCH * N;
            #pragma unroll
            for (int q = 0; q < PHCH / 2; q++) {
                const int m = tid + 256 * q;
                const int r = m >> 7, c4 = (m & 127) << 2;
                cpa16(buf + r * 512 + c4, src + (size_t)r * N + c4);
            }
            asm volatile("cp.async.commit_group;");
            asm volatile("cp.async.wait_group 1;");
        } else {
            asm volatile("cp.async.wait_group 0;");
        }
        __syncthreads();

        const float* vb = v_s + (ch & 1) * PHCH * 512;
        const int g0 = ch * PHCH;
        #pragma unroll
        for (int hh = 0; hh < PHCH; hh += 2) {
            const u64 v0 = *(const u64*)&vb[hh * 512 + 2 * tid];
            const u64 v1 = *(const u64*)&vb[(hh + 1) * 512 + 2 * tid];
            const ulonglong2 ww = *(const ulonglong2*)&w2s[g0 + hh];
            #pragma unroll
            for (int i = 0; i < 4; i++) {
                const ulonglong2 uu = *(const ulonglong2*)&u2s[i * 512 + g0 + hh];
                u64 t = add2(uu.x, v0);
                float2 f = upk(t);
                fma2(acc[i], pk(fmaxf(f.x, 0.f), fmaxf(f.y, 0.f)), ww.x);
                t = add2(uu.y, v1);
                f = upk(t);
                fma2(acc[i], pk(fmaxf(f.x, 0.f), fmaxf(f.y, 0.f)), ww.y);
            }
        }
        __syncthreads();
    }

    #pragma unroll
    for (int i = 0; i < 4; i++)
        ((u64*)(p_s + i * 512))[tid] = acc[i];
    __syncthreads();

    // softmax: warps 0..3 handle rows 0..3
    const int warp = tid >> 5, lane = tid & 31;
    if (warp < 4) {
        float* prow = p_s + warp * 512;
        float m = -1e30f;
        for (int j = lane; j < N; j += 32) m = fmaxf(m, prow[j]);
        #pragma unroll
        for (int o = 16; o; o >>= 1) m = fmaxf(m, __shfl_xor_sync(0xffffffffu, m, o));
        float s = 0.f;
        for (int j = lane; j < N; j += 32) {
            float e = __expf(prow[j] - m);
            prow[j] = e;
            s += e;
        }
        #pragma unroll
        for (int o = 16; o; o >>= 1) s += __shfl_xor_sync(0xffffffffu, s, o);
        if (lane == 0) inv_s[warp] = 1.f / s;
    }
    __syncthreads();

    #pragma unroll
    for (int e = 0; e < 2; e++) {
        const int m = tid + 256 * e;
        const int i = m >> 7, jj = m & 127;
        float4 v = ((const float4*)(p_s + i * 512))[jj];
        const float s = inv_s[i];
        v.x *= s; v.y *= s; v.z *= s; v.w *= s;
        ((float4*)(g_a + (size_t)(i0 + i) * N))[jj] = v;
    }
}

// ---------------------------------------------------------------------------
// Kernel 4: out = a @ he, c-pair packed. Tile 32i x 64c, 256 threads
// (thread = 2i x 2 c-pairs), grid (8,16)=128 CTAs, double-buffered 32-k.
// ---------------------------------------------------------------------------
#define OHST 68

__global__ __launch_bounds__(256) void out_gemm_kernel(
    const float* __restrict__ he, float* __restrict__ out)
{
    __shared__ float he_s[2][32 * OHST];  // [k][c] natural rows + pad
    __shared__ u64  a2s[2][32 * 32];      // [i][k] duplicated pairs

    const int c0 = blockIdx.x * 64;
    const int i0 = blockIdx.y * 32;
    const int tid = threadIdx.x;
    const int tx = tid & 15;
    const int ty = tid >> 4;

    const int ar = tid >> 3;              // 0..31
    const int akq = (tid & 7) << 2;       // 0..28

    float areg[4];

    // prologue
    {
        float4 v = *(const float4*)&g_a[(size_t)(i0 + ar) * N + akq];
        areg[0] = v.x; areg[1] = v.y; areg[2] = v.z; areg[3] = v.w;
        #pragma unroll
        for (int e = 0; e < 4; e++)
            a2s[0][ar * 32 + akq + e] = pk(areg[e], areg[e]);
        #pragma unroll
        for (int q = 0; q < 2; q++) {
            const int m = tid + 256 * q;
            const int k = m >> 4, cq = (m & 15) << 2;
            cpa16(&he_s[0][k * OHST + cq], &he[(size_t)k * D + c0 + cq]);
        }
        asm volatile("cp.async.commit_group;");
    }

    u64 acc[2][2] = {};

    for (int ch = 0; ch < 16; ch++) {
        if (ch + 1 < 16) {
            const int k0 = (ch + 1) * 32;
            float4 v = *(const float4*)&g_a[(size_t)(i0 + ar) * N + k0 + akq];
            areg[0] = v.x; areg[1] = v.y; areg[2] = v.z; areg[3] = v.w;
            float* hd = he_s[(ch + 1) & 1];
            #pragma unroll
            for (int q = 0; q < 2; q++) {
                const int m = tid + 256 * q;
                const int k = m >> 4, cq = (m & 15) << 2;
                cpa16(&hd[k * OHST + cq], &he[(size_t)(k0 + k) * D + c0 + cq]);
            }
            asm volatile("cp.async.commit_group;");
            asm volatile("cp.async.wait_group 1;");
        } else {
            asm volatile("cp.async.wait_group 0;");
        }
        __syncthreads();

        const float* hb = he_s[ch & 1];
        const u64* ab = a2s[ch & 1];
        #pragma unroll
        for (int k = 0; k < 32; k++) {
            ulonglong2 bb = *(const ulonglong2*)&hb[k * OHST + 4 * tx];
            #pragma unroll
            for (int r = 0; r < 2; r++) {
                const u64 aa = ab[(ty + 16 * r) * 32 + k];
                fma2(acc[r][0], aa, bb.x);
                fma2(acc[r][1], aa, bb.y);
            }
        }

        if (ch + 1 < 16) {
            #pragma unroll
            for (int e = 0; e < 4; e++)
                a2s[(ch + 1) & 1][ar * 32 + akq + e] = pk(areg[e], areg[e]);
        }
        __syncthreads();
    }

    #pragma unroll
    for (int r = 0; r < 2; r++) {
        float2 f0 = upk(acc[r][0]);
        float2 f1 = upk(acc[r][1]);
        float4 o = make_float4(f0.x, f0.y, f1.x, f1.y);
        *(float4*)&out[(size_t)(i0 + ty + 16 * r) * D + c0 + 4 * tx] = o;
    }
}

// ---------------------------------------------------------------------------
extern "C" void kernel_launch(void* const* d_in, const int* in_sizes, int n_in,
                              void* d_out, int out_size)
{
    const float* he  = (const float*)d_in[0];   // (512, 512)
    const float* W0w = (const float*)d_in[1];   // (512, 1024)
    const float* W0b = (const float*)d_in[2];   // (512,)
    const float* W1w = (const float*)d_in[3];   // (1, 512)
    // d_in[4] = W1_b: softmax shift-invariant -> unused
    float* out = (float*)d_out;

    const size_t smemG = (size_t)(4 * 128 * GST) * sizeof(float);     // ~73.7KB
    const size_t smemP = (size_t)(2 * PHCH * 512) * sizeof(float)     // v
                       + (size_t)(4 * 512 + 512) * sizeof(u64)        // u2s + w2s
                       + (size_t)(4 * 512 + 8) * sizeof(float);       // p_s + inv
    cudaFuncSetAttribute(uv_gemm_kernel,
                         cudaFuncAttributeMaxDynamicSharedMemorySize, (int)smemG);
    cudaFuncSetAttribute(pairwise_kernel,
                         cudaFuncAttributeMaxDynamicSharedMemorySize, (int)smemP);

    dim3 gG(8, 4, 4);                            // 128 CTAs x 256 thr
    uv_gemm_kernel<<<gG, 256, smemG>>>(he, W0w);

    reduce_kernel<<<128, 256>>>(W0b);

    pairwise_kernel<<<N / 4, 256, smemP>>>(W1w); // 128 CTAs x 256 thr

    dim3 gC(8, 16);                              // 128 CTAs x 256 thr
    out_gemm_kernel<<<gC, 256>>>(he, out);
}